// round 1
// baseline (speedup 1.0000x reference)
#include <cuda_runtime.h>
#include <stdint.h>

#define NB 4
#define SEQ 2048
#define CH 512
#define NH 8
#define HD 64
#define SCALE 0.125f
#define PAD 72

// ---------------- device scratch (allocation-free rule: static globals) ----------------
__device__ float g_Q[(size_t)NB * NH * SEQ * HD];
__device__ float g_K[(size_t)NB * NH * SEQ * HD];
__device__ float g_V[(size_t)NB * NH * SEQ * HD];
__device__ float g_attn[(size_t)NB * SEQ * CH];

// ---------------- accurate fp32 log (Cephes-style, ~1-2 ulp, fast-math-proof) ----------
__device__ __forceinline__ float alogf(float x) {
    // x is a positive normal here (u in [2^-126, 1), t in [5.9e-8, 88])
    uint32_t bits = __float_as_uint(x);
    int e = (int)(bits >> 23) - 126;
    float m = __uint_as_float((bits & 0x007fffffu) | 0x3f000000u); // [0.5, 1)
    if (m < 0.70710678f) { m = m + m; e -= 1; }
    float xm = m - 1.0f;
    float z = xm * xm;
    float y = 7.0376836292e-2f;
    y = fmaf(y, xm, -1.1514610310e-1f);
    y = fmaf(y, xm,  1.1676998740e-1f);
    y = fmaf(y, xm, -1.2420140846e-1f);
    y = fmaf(y, xm,  1.4249322787e-1f);
    y = fmaf(y, xm, -1.6668057665e-1f);
    y = fmaf(y, xm,  2.0000714765e-1f);
    y = fmaf(y, xm, -2.4999993993e-1f);
    y = fmaf(y, xm,  3.3333331174e-1f);
    y = y * xm * z;
    float fe = (float)e;
    y = fmaf(-2.12194440e-4f, fe, y);
    y = fmaf(-0.5f, z, y);
    float r = xm + y;
    r = fmaf(0.693359375f, fe, r);
    return r;
}

// ---------------- JAX threefry2x32, partitionable mode: bits = o0 ^ o1 ------------------
// key = jax.random.key(42) -> (0, 42); counter hi = 0 (size 2^27 < 2^32), lo = flat idx.
__device__ __forceinline__ float gumbel_at(uint32_t idx) {
    const uint32_t ks0 = 0u, ks1 = 42u, ks2 = 0x1BD11BF0u; // 0 ^ 42 ^ 0x1BD11BDA
    uint32_t x0 = ks0;        // 0 + ks0
    uint32_t x1 = idx + ks1;
#define TF_R(r) { x0 += x1; x1 = (x1 << (r)) | (x1 >> (32 - (r))); x1 ^= x0; }
    TF_R(13) TF_R(15) TF_R(26) TF_R(6)   x0 += ks1; x1 += ks2 + 1u;
    TF_R(17) TF_R(29) TF_R(16) TF_R(24)  x0 += ks2; x1 += ks0 + 2u;
    TF_R(13) TF_R(15) TF_R(26) TF_R(6)   x0 += ks0; x1 += ks1 + 3u;
    TF_R(17) TF_R(29) TF_R(16) TF_R(24)  x0 += ks1; x1 += ks2 + 4u;
    TF_R(13) TF_R(15) TF_R(26) TF_R(6)   x0 += ks2; x1 += ks0 + 5u;
#undef TF_R
    uint32_t bits = x0 ^ x1;
    float f = __uint_as_float((bits >> 9) | 0x3f800000u) - 1.0f;  // [0, 1)
    float u = f + 1.17549435e-38f;                                // uniform(tiny, 1)
    return -alogf(-alogf(u));
}

// ---------------- generic projection GEMM: out = X @ W^T + b ---------------------------
// X: [B, SEQ, CH] rows; W: [CH, CH] (row j = output channel, K-major). 64x64 tile, 256 thr,
// 4x4 microtile per thread, smem staged transposed for conflict-free float4 reads.
template <bool HEADSPLIT>
__global__ __launch_bounds__(256) void proj_kernel(
    const float* __restrict__ X, const float* __restrict__ W,
    const float* __restrict__ bias, float* __restrict__ out)
{
    __shared__ float As[32 * PAD];   // As[kc][n]
    __shared__ float Ws[32 * PAD];   // Ws[kc][j]
    const int b  = blockIdx.z;
    const int n0 = blockIdx.x * 64;
    const int j0 = blockIdx.y * 64;
    const int t  = threadIdx.x;
    const int tx = t & 15, ty = t >> 4;
    const float* Xb = X + (size_t)b * SEQ * CH;

    float acc[4][4] = {};
    for (int k0 = 0; k0 < CH; k0 += 32) {
        __syncthreads();
        #pragma unroll
        for (int p = 0; p < 2; p++) {
            int idx = t + p * 256;
            int r = idx >> 3;
            int c = (idx & 7) * 4;
            float4 a = *reinterpret_cast<const float4*>(&Xb[(size_t)(n0 + r) * CH + k0 + c]);
            As[(c + 0) * PAD + r] = a.x; As[(c + 1) * PAD + r] = a.y;
            As[(c + 2) * PAD + r] = a.z; As[(c + 3) * PAD + r] = a.w;
            float4 w = *reinterpret_cast<const float4*>(&W[(size_t)(j0 + r) * CH + k0 + c]);
            Ws[(c + 0) * PAD + r] = w.x; Ws[(c + 1) * PAD + r] = w.y;
            Ws[(c + 2) * PAD + r] = w.z; Ws[(c + 3) * PAD + r] = w.w;
        }
        __syncthreads();
        #pragma unroll
        for (int kc = 0; kc < 32; kc++) {
            float4 av = *reinterpret_cast<const float4*>(&As[kc * PAD + ty * 4]);
            float4 wv = *reinterpret_cast<const float4*>(&Ws[kc * PAD + tx * 4]);
            float a[4] = {av.x, av.y, av.z, av.w};
            float w[4] = {wv.x, wv.y, wv.z, wv.w};
            #pragma unroll
            for (int i = 0; i < 4; i++)
                #pragma unroll
                for (int j = 0; j < 4; j++)
                    acc[i][j] = fmaf(a[i], w[j], acc[i][j]);
        }
    }
    #pragma unroll
    for (int i = 0; i < 4; i++) {
        int n = n0 + ty * 4 + i;
        #pragma unroll
        for (int j = 0; j < 4; j++) {
            int jj = j0 + tx * 4 + j;
            float v = acc[i][j] + bias[jj];
            if (HEADSPLIT) {
                out[(((size_t)b * NH + (jj >> 6)) * SEQ + n) * HD + (jj & 63)] = v;
            } else {
                out[((size_t)b * SEQ + n) * CH + jj] = v;
            }
        }
    }
}

// ---------------- flash attention with on-the-fly gumbel -------------------------------
// Block = (64 q-rows, one (b,h)); streams 64-key tiles with online softmax.
__global__ __launch_bounds__(256, 2) void attn_kernel(
    const float* __restrict__ Q, const float* __restrict__ K,
    const float* __restrict__ V, float* __restrict__ out)
{
    extern __shared__ float sm[];
    float* Qs  = sm;                  // [HD][PAD] transposed: Qs[d][r]
    float* Ks  = Qs + 64 * PAD;       // [HD][PAD] transposed: Ks[d][c]
    float* Vs  = Ks + 64 * PAD;       // [64][PAD]: Vs[kk][d]
    float* Ss  = Vs + 64 * PAD;       // [64][PAD]: raw S [r][c], then P transposed [c][r]
    float* m_s = Ss + 64 * PAD;       // [64]
    float* l_s = m_s + 64;            // [64]
    float* c_s = l_s + 64;            // [64]

    const int b  = blockIdx.z, h = blockIdx.y;
    const int n0 = blockIdx.x * 64;
    const int t  = threadIdx.x;
    const int tx = t & 15, ty = t >> 4;   // 16x16 microtile grid
    const int r4 = t >> 2, cl = t & 3;    // softmax: 4 threads per row

    const float* Qg = Q + (((size_t)b * NH + h) * SEQ + n0) * HD;
    const float* Kg = K + ((size_t)b * NH + h) * SEQ * HD;
    const float* Vg = V + ((size_t)b * NH + h) * SEQ * HD;

    #pragma unroll
    for (int p = 0; p < 4; p++) {
        int idx = t + p * 256;
        int r = idx >> 4;
        int d = (idx & 15) * 4;
        float4 v = *reinterpret_cast<const float4*>(&Qg[r * HD + d]);
        Qs[(d + 0) * PAD + r] = v.x; Qs[(d + 1) * PAD + r] = v.y;
        Qs[(d + 2) * PAD + r] = v.z; Qs[(d + 3) * PAD + r] = v.w;
    }
    if (t < 64) { m_s[t] = -3.402823466e38f; l_s[t] = 0.f; }

    float O[4][4] = {};
    const uint32_t rowbase = (((uint32_t)(b * NH + h) << 11) + (uint32_t)(n0 + r4)) << 11;

    for (int k0 = 0; k0 < SEQ; k0 += 64) {
        __syncthreads();   // prev-iter consumers of Ks/Vs/Ss done; Qs ready on iter 0
        #pragma unroll
        for (int p = 0; p < 4; p++) {
            int idx = t + p * 256;
            int r = idx >> 4;
            int d = (idx & 15) * 4;
            float4 kv = *reinterpret_cast<const float4*>(&Kg[(size_t)(k0 + r) * HD + d]);
            Ks[(d + 0) * PAD + r] = kv.x; Ks[(d + 1) * PAD + r] = kv.y;
            Ks[(d + 2) * PAD + r] = kv.z; Ks[(d + 3) * PAD + r] = kv.w;
            *reinterpret_cast<float4*>(&Vs[r * PAD + d]) =
                *reinterpret_cast<const float4*>(&Vg[(size_t)(k0 + r) * HD + d]);
        }
        __syncthreads();

        // --- S = Q K^T (raw, unscaled), each thread a 4x4 tile ---
        float S[4][4] = {};
        #pragma unroll 16
        for (int d = 0; d < HD; d++) {
            float4 qv = *reinterpret_cast<const float4*>(&Qs[d * PAD + ty * 4]);
            float4 kv = *reinterpret_cast<const float4*>(&Ks[d * PAD + tx * 4]);
            float a[4] = {qv.x, qv.y, qv.z, qv.w};
            float w[4] = {kv.x, kv.y, kv.z, kv.w};
            #pragma unroll
            for (int i = 0; i < 4; i++)
                #pragma unroll
                for (int j = 0; j < 4; j++)
                    S[i][j] = fmaf(a[i], w[j], S[i][j]);
        }
        #pragma unroll
        for (int i = 0; i < 4; i++)
            *reinterpret_cast<float4*>(&Ss[(ty * 4 + i) * PAD + tx * 4]) =
                make_float4(S[i][0], S[i][1], S[i][2], S[i][3]);
        __syncthreads();

        // --- online softmax with gumbel noise; row r4, 16 cols per thread ---
        float sv[16];
        float mx = -3.402823466e38f;
        #pragma unroll
        for (int ii = 0; ii < 16; ii++) {
            int c = cl + ii * 4;
            float s = fmaf(Ss[r4 * PAD + c], SCALE, gumbel_at(rowbase + (uint32_t)(k0 + c)));
            sv[ii] = s;
            mx = fmaxf(mx, s);
        }
        mx = fmaxf(mx, __shfl_xor_sync(0xffffffffu, mx, 1));
        mx = fmaxf(mx, __shfl_xor_sync(0xffffffffu, mx, 2));
        float m_old = m_s[r4];
        float m_new = fmaxf(m_old, mx);
        float corr  = __expf(m_old - m_new);
        __syncthreads();   // all reads of Ss[r][c] done before transposed writes
        float ls = 0.f;
        #pragma unroll
        for (int ii = 0; ii < 16; ii++) {
            int c = cl + ii * 4;
            float p = __expf(sv[ii] - m_new);
            ls += p;
            Ss[c * PAD + r4] = p;          // store P transposed: Ps[c][r]
        }
        ls += __shfl_xor_sync(0xffffffffu, ls, 1);
        ls += __shfl_xor_sync(0xffffffffu, ls, 2);
        if (cl == 0) {
            l_s[r4] = fmaf(l_s[r4], corr, ls);
            m_s[r4] = m_new;
            c_s[r4] = corr;
        }
        __syncthreads();

        // --- O = O*corr + P V ---
        float cr[4];
        #pragma unroll
        for (int i = 0; i < 4; i++) cr[i] = c_s[ty * 4 + i];
        #pragma unroll
        for (int i = 0; i < 4; i++)
            #pragma unroll
            for (int j = 0; j < 4; j++)
                O[i][j] *= cr[i];
        #pragma unroll 16
        for (int kk = 0; kk < 64; kk++) {
            float4 pv = *reinterpret_cast<const float4*>(&Ss[kk * PAD + ty * 4]);
            float4 vv = *reinterpret_cast<const float4*>(&Vs[kk * PAD + tx * 4]);
            float p[4] = {pv.x, pv.y, pv.z, pv.w};
            float v[4] = {vv.x, vv.y, vv.z, vv.w};
            #pragma unroll
            for (int i = 0; i < 4; i++)
                #pragma unroll
                for (int j = 0; j < 4; j++)
                    O[i][j] = fmaf(p[i], v[j], O[i][j]);
        }
    }

    // epilogue: normalize and write [B, N, C] with c = h*64 + d
    #pragma unroll
    for (int i = 0; i < 4; i++) {
        int rr = ty * 4 + i;
        float inv = 1.0f / l_s[rr];
        float4 o = make_float4(O[i][0] * inv, O[i][1] * inv, O[i][2] * inv, O[i][3] * inv);
        *reinterpret_cast<float4*>(
            &out[((size_t)b * SEQ + n0 + rr) * CH + h * HD + tx * 4]) = o;
    }
}

// ---------------- launch ----------------------------------------------------------------
extern "C" void kernel_launch(void* const* d_in, const int* in_sizes, int n_in,
                              void* d_out, int out_size)
{
    (void)in_sizes; (void)n_in; (void)out_size;
    const float* x  = (const float*)d_in[0];
    const float* y  = (const float*)d_in[1];
    const float* z  = (const float*)d_in[2];
    const float* Wq = (const float*)d_in[3];
    const float* bq = (const float*)d_in[4];
    const float* Wk = (const float*)d_in[5];
    const float* bk = (const float*)d_in[6];
    const float* Wv = (const float*)d_in[7];
    const float* bv = (const float*)d_in[8];
    const float* Wo = (const float*)d_in[9];
    const float* bo = (const float*)d_in[10];
    float* out = (float*)d_out;

    float *qp, *kp, *vp, *ap;
    cudaGetSymbolAddress((void**)&qp, g_Q);
    cudaGetSymbolAddress((void**)&kp, g_K);
    cudaGetSymbolAddress((void**)&vp, g_V);
    cudaGetSymbolAddress((void**)&ap, g_attn);

    dim3 pb(256);
    dim3 pg(SEQ / 64, CH / 64, NB);
    proj_kernel<true><<<pg, pb>>>(x, Wq, bq, qp);
    proj_kernel<true><<<pg, pb>>>(y, Wk, bk, kp);
    proj_kernel<true><<<pg, pb>>>(z, Wv, bv, vp);

    const int SMEM = (4 * 64 * PAD + 192) * 4;  // 74496 B
    cudaFuncSetAttribute(attn_kernel, cudaFuncAttributeMaxDynamicSharedMemorySize, SMEM);
    dim3 ag(SEQ / 64, NH, NB);
    attn_kernel<<<ag, pb, SMEM>>>(qp, kp, vp, ap);

    proj_kernel<false><<<pg, pb>>>(ap, Wo, bo, out);
}

// round 2
// speedup vs baseline: 2.2446x; 2.2446x over previous
#include <cuda_runtime.h>
#include <stdint.h>

#define NB 4
#define SEQ 2048
#define CH 512
#define NH 8
#define HD 64
#define SCALE 0.125f
#define NEGINF -3.402823466e38f

// ---------------- device scratch (allocation-free rule: static globals) ----------------
__device__ float g_Q[(size_t)NB * NH * SEQ * HD];
__device__ float g_K[(size_t)NB * NH * SEQ * HD];
__device__ float g_V[(size_t)NB * NH * SEQ * HD];
__device__ float g_attn[(size_t)NB * SEQ * CH];

// ---------------- helpers ---------------------------------------------------------------
__device__ __forceinline__ uint32_t f2tf(float f) {
    uint32_t r;
    asm("cvt.rna.tf32.f32 %0, %1;" : "=r"(r) : "f"(f));
    return r;
}

__device__ __forceinline__ void mma8(float& d0, float& d1, float& d2, float& d3,
                                     uint32_t a0, uint32_t a1, uint32_t a2, uint32_t a3,
                                     uint32_t b0, uint32_t b1) {
    asm volatile(
        "mma.sync.aligned.m16n8k8.row.col.f32.tf32.tf32.f32 "
        "{%0,%1,%2,%3},{%4,%5,%6,%7},{%8,%9},{%0,%1,%2,%3};"
        : "+f"(d0), "+f"(d1), "+f"(d2), "+f"(d3)
        : "r"(a0), "r"(a1), "r"(a2), "r"(a3), "r"(b0), "r"(b1));
}

// ---------------- accurate fp32 log (Cephes-style, ~1-2 ulp, fast-math-proof) ----------
__device__ __forceinline__ float alogf(float x) {
    uint32_t bits = __float_as_uint(x);
    int e = (int)(bits >> 23) - 126;
    float m = __uint_as_float((bits & 0x007fffffu) | 0x3f000000u); // [0.5, 1)
    if (m < 0.70710678f) { m = m + m; e -= 1; }
    float xm = m - 1.0f;
    float z = xm * xm;
    float y = 7.0376836292e-2f;
    y = fmaf(y, xm, -1.1514610310e-1f);
    y = fmaf(y, xm,  1.1676998740e-1f);
    y = fmaf(y, xm, -1.2420140846e-1f);
    y = fmaf(y, xm,  1.4249322787e-1f);
    y = fmaf(y, xm, -1.6668057665e-1f);
    y = fmaf(y, xm,  2.0000714765e-1f);
    y = fmaf(y, xm, -2.4999993993e-1f);
    y = fmaf(y, xm,  3.3333331174e-1f);
    y = y * xm * z;
    float fe = (float)e;
    y = fmaf(-2.12194440e-4f, fe, y);
    y = fmaf(-0.5f, z, y);
    float r = xm + y;
    r = fmaf(0.693359375f, fe, r);
    return r;
}

// ---------------- JAX threefry2x32, partitionable mode: bits = o0 ^ o1 ------------------
__device__ __forceinline__ float gumbel_at(uint32_t idx) {
    const uint32_t ks0 = 0u, ks1 = 42u, ks2 = 0x1BD11BF0u;
    uint32_t x0 = ks0;
    uint32_t x1 = idx + ks1;
#define TF_R(r) { x0 += x1; x1 = __funnelshift_l(x1, x1, (r)); x1 ^= x0; }
    TF_R(13) TF_R(15) TF_R(26) TF_R(6)   x0 += ks1; x1 += ks2 + 1u;
    TF_R(17) TF_R(29) TF_R(16) TF_R(24)  x0 += ks2; x1 += ks0 + 2u;
    TF_R(13) TF_R(15) TF_R(26) TF_R(6)   x0 += ks0; x1 += ks1 + 3u;
    TF_R(17) TF_R(29) TF_R(16) TF_R(24)  x0 += ks1; x1 += ks2 + 4u;
    TF_R(13) TF_R(15) TF_R(26) TF_R(6)   x0 += ks2; x1 += ks0 + 5u;
#undef TF_R
    uint32_t bits = x0 ^ x1;
    float f = __uint_as_float((bits >> 9) | 0x3f800000u) - 1.0f;
    float u = f + 1.17549435e-38f;
    return -alogf(-alogf(u));
}

// ---------------- projection GEMM via tf32 mma: out = X @ W^T + b ----------------------
// Block tile 128x128, BK=32, 8 warps (warp tile 64x32). Smem ld=36 (4 mod 32) makes
// the m16n8k8 fragment LDS pattern conflict-free.
template <bool HEADSPLIT>
__global__ __launch_bounds__(256, 2) void proj_mma(
    const float* __restrict__ X, const float* __restrict__ W,
    const float* __restrict__ bias, float* __restrict__ out)
{
    __shared__ uint32_t As[128 * 36];
    __shared__ uint32_t Ws[128 * 36];
    const int b  = blockIdx.z;
    const int n0 = blockIdx.x * 128;
    const int j0 = blockIdx.y * 128;
    const int t  = threadIdx.x;
    const int w  = t >> 5, lane = t & 31;
    const int wm = w & 1, wn = w >> 1;          // 2 x 4 warp grid
    const int g  = lane >> 2, tig = lane & 3;
    const float* Xb = X + (size_t)b * SEQ * CH;

    float acc[4][4][4];
    #pragma unroll
    for (int mt = 0; mt < 4; mt++)
        #pragma unroll
        for (int nt = 0; nt < 4; nt++)
            #pragma unroll
            for (int q = 0; q < 4; q++) acc[mt][nt][q] = 0.f;

    float4 pa[4], pw[4];
    #pragma unroll
    for (int p = 0; p < 4; p++) {
        int i = p * 256 + t; int r = i >> 3; int c4 = (i & 7) * 4;
        pa[p] = *(const float4*)&Xb[(size_t)(n0 + r) * CH + c4];
        pw[p] = *(const float4*)&W[(size_t)(j0 + r) * CH + c4];
    }

    for (int k0 = 0; k0 < CH; k0 += 32) {
        __syncthreads();
        #pragma unroll
        for (int p = 0; p < 4; p++) {
            int i = p * 256 + t; int r = i >> 3; int c4 = (i & 7) * 4;
            As[r * 36 + c4 + 0] = f2tf(pa[p].x);
            As[r * 36 + c4 + 1] = f2tf(pa[p].y);
            As[r * 36 + c4 + 2] = f2tf(pa[p].z);
            As[r * 36 + c4 + 3] = f2tf(pa[p].w);
            Ws[r * 36 + c4 + 0] = f2tf(pw[p].x);
            Ws[r * 36 + c4 + 1] = f2tf(pw[p].y);
            Ws[r * 36 + c4 + 2] = f2tf(pw[p].z);
            Ws[r * 36 + c4 + 3] = f2tf(pw[p].w);
        }
        __syncthreads();
        if (k0 + 32 < CH) {
            #pragma unroll
            for (int p = 0; p < 4; p++) {
                int i = p * 256 + t; int r = i >> 3; int c4 = (i & 7) * 4;
                pa[p] = *(const float4*)&Xb[(size_t)(n0 + r) * CH + k0 + 32 + c4];
                pw[p] = *(const float4*)&W[(size_t)(j0 + r) * CH + k0 + 32 + c4];
            }
        }
        #pragma unroll
        for (int ks = 0; ks < 4; ks++) {
            const int kb = ks * 8;
            uint32_t af[4][4], bf[4][2];
            #pragma unroll
            for (int mt = 0; mt < 4; mt++) {
                int m = wm * 64 + mt * 16;
                af[mt][0] = As[(m + g) * 36 + kb + tig];
                af[mt][1] = As[(m + g + 8) * 36 + kb + tig];
                af[mt][2] = As[(m + g) * 36 + kb + tig + 4];
                af[mt][3] = As[(m + g + 8) * 36 + kb + tig + 4];
            }
            #pragma unroll
            for (int nt = 0; nt < 4; nt++) {
                int n = wn * 32 + nt * 8;
                bf[nt][0] = Ws[(n + g) * 36 + kb + tig];
                bf[nt][1] = Ws[(n + g) * 36 + kb + tig + 4];
            }
            #pragma unroll
            for (int mt = 0; mt < 4; mt++)
                #pragma unroll
                for (int nt = 0; nt < 4; nt++)
                    mma8(acc[mt][nt][0], acc[mt][nt][1], acc[mt][nt][2], acc[mt][nt][3],
                         af[mt][0], af[mt][1], af[mt][2], af[mt][3],
                         bf[nt][0], bf[nt][1]);
        }
    }

    #pragma unroll
    for (int mt = 0; mt < 4; mt++) {
        int n = n0 + wm * 64 + mt * 16 + g;
        #pragma unroll
        for (int nt = 0; nt < 4; nt++) {
            int j = j0 + wn * 32 + nt * 8 + 2 * tig;
            float2 bj = *(const float2*)&bias[j];
            float2 v0 = make_float2(acc[mt][nt][0] + bj.x, acc[mt][nt][1] + bj.y);
            float2 v1 = make_float2(acc[mt][nt][2] + bj.x, acc[mt][nt][3] + bj.y);
            if (HEADSPLIT) {
                size_t base = (((size_t)b * NH + (j >> 6)) * SEQ) * HD + (j & 63);
                *(float2*)&out[base + (size_t)n * HD]       = v0;
                *(float2*)&out[base + (size_t)(n + 8) * HD] = v1;
            } else {
                *(float2*)&out[((size_t)b * SEQ + n) * CH + j]     = v0;
                *(float2*)&out[((size_t)b * SEQ + n + 8) * CH + j] = v1;
            }
        }
    }
}

// ---------------- flash attention: tf32 mma GEMMs + SIMT gumbel-softmax ----------------
// Block = 64 q-rows x one (b,h). 8 warps in 4(m) x 2(n) grid; warp tile m16 x n32.
// Smem lds: Qs/Ks/Ss ld=68 (4 mod 32), Vs ld=72 (8 mod 32) -> conflict-free fragments.
__global__ __launch_bounds__(256, 2) void attn_mma(
    const float* __restrict__ Q, const float* __restrict__ K,
    const float* __restrict__ V, float* __restrict__ out)
{
    extern __shared__ uint32_t sm[];
    uint32_t* Qs = sm;                       // [64][68] tf32
    uint32_t* Ks = sm + 4352;                // [64][68] tf32
    uint32_t* Vs = sm + 8704;                // [64][72] tf32
    float*    Ss = (float*)(sm + 13312);     // [64][68] f32 S, then tf32 P bits
    uint32_t* Su = sm + 13312;
    float*    m_s = (float*)(sm + 17664);
    float*    l_s = m_s + 64;
    float*    c_s = l_s + 64;

    const int b = blockIdx.z, h = blockIdx.y, n0 = blockIdx.x * 64;
    const int t = threadIdx.x, w = t >> 5, lane = t & 31;
    const int wm = w & 3, wn = w >> 2;
    const int g = lane >> 2, tig = lane & 3;
    const int r4 = t >> 2, cl = t & 3;

    const float* Qg = Q + (((size_t)b * NH + h) * SEQ + n0) * HD;
    const float* Kg = K + ((size_t)b * NH + h) * SEQ * HD;
    const float* Vg = V + ((size_t)b * NH + h) * SEQ * HD;

    #pragma unroll
    for (int p = 0; p < 4; p++) {
        int i = p * 256 + t; int r = i >> 4; int c4 = (i & 15) * 4;
        float4 v = *(const float4*)&Qg[r * HD + c4];
        Qs[r * 68 + c4 + 0] = f2tf(v.x);
        Qs[r * 68 + c4 + 1] = f2tf(v.y);
        Qs[r * 68 + c4 + 2] = f2tf(v.z);
        Qs[r * 68 + c4 + 3] = f2tf(v.w);
    }
    if (t < 64) { m_s[t] = NEGINF; l_s[t] = 0.f; }

    float acc_o[4][4];
    #pragma unroll
    for (int nt = 0; nt < 4; nt++)
        #pragma unroll
        for (int q = 0; q < 4; q++) acc_o[nt][q] = 0.f;

    const uint32_t rowbase = (((uint32_t)(b * NH + h) << 11) + (uint32_t)(n0 + r4)) << 11;

    for (int k0 = 0; k0 < SEQ; k0 += 64) {
        __syncthreads();
        #pragma unroll
        for (int p = 0; p < 4; p++) {
            int i = p * 256 + t; int r = i >> 4; int c4 = (i & 15) * 4;
            float4 kv = *(const float4*)&Kg[(size_t)(k0 + r) * HD + c4];
            Ks[r * 68 + c4 + 0] = f2tf(kv.x);
            Ks[r * 68 + c4 + 1] = f2tf(kv.y);
            Ks[r * 68 + c4 + 2] = f2tf(kv.z);
            Ks[r * 68 + c4 + 3] = f2tf(kv.w);
            float4 vv = *(const float4*)&Vg[(size_t)(k0 + r) * HD + c4];
            Vs[r * 72 + c4 + 0] = f2tf(vv.x);
            Vs[r * 72 + c4 + 1] = f2tf(vv.y);
            Vs[r * 72 + c4 + 2] = f2tf(vv.z);
            Vs[r * 72 + c4 + 3] = f2tf(vv.w);
        }
        __syncthreads();

        // --- S = Q K^T (raw logits, unscaled) ---
        float acc_s[4][4];
        #pragma unroll
        for (int nt = 0; nt < 4; nt++)
            #pragma unroll
            for (int q = 0; q < 4; q++) acc_s[nt][q] = 0.f;
        #pragma unroll
        for (int ks = 0; ks < 8; ks++) {
            const int kb = ks * 8;
            const int m = wm * 16;
            uint32_t a0 = Qs[(m + g) * 68 + kb + tig];
            uint32_t a1 = Qs[(m + g + 8) * 68 + kb + tig];
            uint32_t a2 = Qs[(m + g) * 68 + kb + tig + 4];
            uint32_t a3 = Qs[(m + g + 8) * 68 + kb + tig + 4];
            #pragma unroll
            for (int nt = 0; nt < 4; nt++) {
                int n = wn * 32 + nt * 8;
                uint32_t b0 = Ks[(n + g) * 68 + kb + tig];
                uint32_t b1 = Ks[(n + g) * 68 + kb + tig + 4];
                mma8(acc_s[nt][0], acc_s[nt][1], acc_s[nt][2], acc_s[nt][3],
                     a0, a1, a2, a3, b0, b1);
            }
        }
        #pragma unroll
        for (int nt = 0; nt < 4; nt++) {
            int rr = wm * 16 + g;
            int cc = wn * 32 + nt * 8 + 2 * tig;
            *(float2*)&Ss[rr * 68 + cc]       = make_float2(acc_s[nt][0], acc_s[nt][1]);
            *(float2*)&Ss[(rr + 8) * 68 + cc] = make_float2(acc_s[nt][2], acc_s[nt][3]);
        }
        __syncthreads();

        // --- online softmax + gumbel; thread owns row r4, cols cl+4i (read+write) ---
        float sv[16];
        float mx = NEGINF;
        #pragma unroll
        for (int ii = 0; ii < 16; ii++) {
            int c = cl + ii * 4;
            float s = fmaf(Ss[r4 * 68 + c], SCALE, gumbel_at(rowbase + (uint32_t)(k0 + c)));
            sv[ii] = s;
            mx = fmaxf(mx, s);
        }
        mx = fmaxf(mx, __shfl_xor_sync(0xffffffffu, mx, 1));
        mx = fmaxf(mx, __shfl_xor_sync(0xffffffffu, mx, 2));
        float m_old = m_s[r4];
        float m_new = fmaxf(m_old, mx);
        float corr  = __expf(m_old - m_new);
        float ls = 0.f;
        #pragma unroll
        for (int ii = 0; ii < 16; ii++) {
            int c = cl + ii * 4;
            float p = __expf(sv[ii] - m_new);
            ls += p;
            Su[r4 * 68 + c] = f2tf(p);     // P as tf32 bits, row-major in place
        }
        ls += __shfl_xor_sync(0xffffffffu, ls, 1);
        ls += __shfl_xor_sync(0xffffffffu, ls, 2);
        if (cl == 0) {
            l_s[r4] = fmaf(l_s[r4], corr, ls);
            m_s[r4] = m_new;
            c_s[r4] = corr;
        }
        __syncthreads();

        // --- O = O*corr + P V ---
        float cr0 = c_s[wm * 16 + g], cr1 = c_s[wm * 16 + g + 8];
        #pragma unroll
        for (int nt = 0; nt < 4; nt++) {
            acc_o[nt][0] *= cr0; acc_o[nt][1] *= cr0;
            acc_o[nt][2] *= cr1; acc_o[nt][3] *= cr1;
        }
        #pragma unroll
        for (int ks = 0; ks < 8; ks++) {
            const int kb = ks * 8;
            const int m = wm * 16;
            uint32_t a0 = Su[(m + g) * 68 + kb + tig];
            uint32_t a1 = Su[(m + g + 8) * 68 + kb + tig];
            uint32_t a2 = Su[(m + g) * 68 + kb + tig + 4];
            uint32_t a3 = Su[(m + g + 8) * 68 + kb + tig + 4];
            #pragma unroll
            for (int nt = 0; nt < 4; nt++) {
                int n = wn * 32 + nt * 8;
                uint32_t b0 = Vs[(kb + tig) * 72 + n + g];
                uint32_t b1 = Vs[(kb + tig + 4) * 72 + n + g];
                mma8(acc_o[nt][0], acc_o[nt][1], acc_o[nt][2], acc_o[nt][3],
                     a0, a1, a2, a3, b0, b1);
            }
        }
    }

    // epilogue: normalize and write [B, N, C] with c = h*64 + d
    float inv0 = 1.0f / l_s[wm * 16 + g];
    float inv1 = 1.0f / l_s[wm * 16 + g + 8];
    #pragma unroll
    for (int nt = 0; nt < 4; nt++) {
        int rr = n0 + wm * 16 + g;
        int d  = wn * 32 + nt * 8 + 2 * tig;
        *(float2*)&out[((size_t)b * SEQ + rr) * CH + h * HD + d] =
            make_float2(acc_o[nt][0] * inv0, acc_o[nt][1] * inv0);
        *(float2*)&out[((size_t)b * SEQ + rr + 8) * CH + h * HD + d] =
            make_float2(acc_o[nt][2] * inv1, acc_o[nt][3] * inv1);
    }
}

// ---------------- launch ----------------------------------------------------------------
extern "C" void kernel_launch(void* const* d_in, const int* in_sizes, int n_in,
                              void* d_out, int out_size)
{
    (void)in_sizes; (void)n_in; (void)out_size;
    const float* x  = (const float*)d_in[0];
    const float* y  = (const float*)d_in[1];
    const float* z  = (const float*)d_in[2];
    const float* Wq = (const float*)d_in[3];
    const float* bq = (const float*)d_in[4];
    const float* Wk = (const float*)d_in[5];
    const float* bk = (const float*)d_in[6];
    const float* Wv = (const float*)d_in[7];
    const float* bv = (const float*)d_in[8];
    const float* Wo = (const float*)d_in[9];
    const float* bo = (const float*)d_in[10];
    float* out = (float*)d_out;

    float *qp, *kp, *vp, *ap;
    cudaGetSymbolAddress((void**)&qp, g_Q);
    cudaGetSymbolAddress((void**)&kp, g_K);
    cudaGetSymbolAddress((void**)&vp, g_V);
    cudaGetSymbolAddress((void**)&ap, g_attn);

    dim3 pb(256);
    dim3 pg(SEQ / 128, CH / 128, NB);
    proj_mma<true><<<pg, pb>>>(x, Wq, bq, qp);
    proj_mma<true><<<pg, pb>>>(y, Wk, bk, kp);
    proj_mma<true><<<pg, pb>>>(z, Wv, bv, vp);

    const int SMEM = 17856 * 4;  // 71424 B
    cudaFuncSetAttribute(attn_mma, cudaFuncAttributeMaxDynamicSharedMemorySize, SMEM);
    dim3 ag(SEQ / 64, NH, NB);
    attn_mma<<<ag, pb, SMEM>>>(qp, kp, vp, ap);

    proj_mma<false><<<pg, pb>>>(ap, Wo, bo, out);
}

// round 3
// speedup vs baseline: 2.6528x; 1.1819x over previous
#include <cuda_runtime.h>
#include <stdint.h>

#define NB 4
#define SEQ 2048
#define CH 512
#define NH 8
#define HD 64
#define SCALE 0.125f
// SCALE * log2(e)
#define SC2 0.18033688011112042f

// ---------------- device scratch (allocation-free rule: static globals) ----------------
__device__ float g_Q[(size_t)NB * NH * SEQ * HD];
__device__ float g_K[(size_t)NB * NH * SEQ * HD];
__device__ float g_V[(size_t)NB * NH * SEQ * HD];
__device__ float g_attn[(size_t)NB * SEQ * CH];

// ---------------- helpers ---------------------------------------------------------------
__device__ __forceinline__ uint32_t f2tf(float f) {
    uint32_t r;
    asm("cvt.rna.tf32.f32 %0, %1;" : "=r"(r) : "f"(f));
    return r;
}

__device__ __forceinline__ float ex2(float x) {
    float r;
    asm("ex2.approx.ftz.f32 %0, %1;" : "=f"(r) : "f"(x));
    return r;
}

__device__ __forceinline__ float frcp(float x) {
    float r;
    asm("rcp.approx.ftz.f32 %0, %1;" : "=f"(r) : "f"(x));
    return r;
}

__device__ __forceinline__ void mma8(float& d0, float& d1, float& d2, float& d3,
                                     uint32_t a0, uint32_t a1, uint32_t a2, uint32_t a3,
                                     uint32_t b0, uint32_t b1) {
    asm volatile(
        "mma.sync.aligned.m16n8k8.row.col.f32.tf32.tf32.f32 "
        "{%0,%1,%2,%3},{%4,%5,%6,%7},{%8,%9},{%0,%1,%2,%3};"
        : "+f"(d0), "+f"(d1), "+f"(d2), "+f"(d3)
        : "r"(a0), "r"(a1), "r"(a2), "r"(a3), "r"(b0), "r"(b1));
}

// ---------------- accurate fp32 log (Cephes-style, ~1-2 ulp, fast-math-proof) ----------
__device__ __forceinline__ float alogf(float x) {
    uint32_t bits = __float_as_uint(x);
    int e = (int)(bits >> 23) - 126;
    float m = __uint_as_float((bits & 0x007fffffu) | 0x3f000000u); // [0.5, 1)
    if (m < 0.70710678f) { m = m + m; e -= 1; }
    float xm = m - 1.0f;
    float z = xm * xm;
    float y = 7.0376836292e-2f;
    y = fmaf(y, xm, -1.1514610310e-1f);
    y = fmaf(y, xm,  1.1676998740e-1f);
    y = fmaf(y, xm, -1.2420140846e-1f);
    y = fmaf(y, xm,  1.4249322787e-1f);
    y = fmaf(y, xm, -1.6668057665e-1f);
    y = fmaf(y, xm,  2.0000714765e-1f);
    y = fmaf(y, xm, -2.4999993993e-1f);
    y = fmaf(y, xm,  3.3333331174e-1f);
    y = y * xm * z;
    float fe = (float)e;
    y = fmaf(-2.12194440e-4f, fe, y);
    y = fmaf(-0.5f, z, y);
    float r = xm + y;
    r = fmaf(0.693359375f, fe, r);
    return r;
}

// ---------------- JAX threefry2x32, partitionable: t = -log(uniform(tiny,1)) ------------
// Returns t (NOT the gumbel): softmax weight uses w = exp(logit*SCALE) / t.
__device__ __forceinline__ float neglog_u_at(uint32_t idx) {
    const uint32_t ks0 = 0u, ks1 = 42u, ks2 = 0x1BD11BF0u;
    uint32_t x0 = ks0;
    uint32_t x1 = idx + ks1;
#define TF_R(r) { x0 += x1; x1 = __funnelshift_l(x1, x1, (r)); x1 ^= x0; }
    TF_R(13) TF_R(15) TF_R(26) TF_R(6)   x0 += ks1; x1 += ks2 + 1u;
    TF_R(17) TF_R(29) TF_R(16) TF_R(24)  x0 += ks2; x1 += ks0 + 2u;
    TF_R(13) TF_R(15) TF_R(26) TF_R(6)   x0 += ks0; x1 += ks1 + 3u;
    TF_R(17) TF_R(29) TF_R(16) TF_R(24)  x0 += ks1; x1 += ks2 + 4u;
    TF_R(13) TF_R(15) TF_R(26) TF_R(6)   x0 += ks2; x1 += ks0 + 5u;
#undef TF_R
    uint32_t bits = x0 ^ x1;
    float f = __uint_as_float((bits >> 9) | 0x3f800000u) - 1.0f;
    float u = f + 1.17549435e-38f;
    return -alogf(u);
}

// ---------------- fused QKV projection GEMM via tf32 mma -------------------------------
// Block tile 128x128, BK=32, 8 warps (warp tile 64x32), smem ld=36 conflict-free.
// blockIdx.z encodes (batch, which-projection).
__global__ __launch_bounds__(256, 2) void proj_qkv(
    const float* __restrict__ x, const float* __restrict__ y, const float* __restrict__ z,
    const float* __restrict__ Wq, const float* __restrict__ bq,
    const float* __restrict__ Wk, const float* __restrict__ bk,
    const float* __restrict__ Wv, const float* __restrict__ bv,
    float* __restrict__ oq, float* __restrict__ ok, float* __restrict__ ov)
{
    __shared__ uint32_t As[128 * 36];
    __shared__ uint32_t Ws[128 * 36];
    const int b     = blockIdx.z & 3;
    const int which = blockIdx.z >> 2;
    const float* X    = (which == 0) ? x  : (which == 1) ? y  : z;
    const float* W    = (which == 0) ? Wq : (which == 1) ? Wk : Wv;
    const float* bias = (which == 0) ? bq : (which == 1) ? bk : bv;
    float* out        = (which == 0) ? oq : (which == 1) ? ok : ov;

    const int n0 = blockIdx.x * 128;
    const int j0 = blockIdx.y * 128;
    const int t  = threadIdx.x;
    const int w  = t >> 5, lane = t & 31;
    const int wm = w & 1, wn = w >> 1;
    const int g  = lane >> 2, tig = lane & 3;
    const float* Xb = X + (size_t)b * SEQ * CH;

    float acc[4][4][4];
    #pragma unroll
    for (int mt = 0; mt < 4; mt++)
        #pragma unroll
        for (int nt = 0; nt < 4; nt++)
            #pragma unroll
            for (int q = 0; q < 4; q++) acc[mt][nt][q] = 0.f;

    float4 pa[4], pw[4];
    #pragma unroll
    for (int p = 0; p < 4; p++) {
        int i = p * 256 + t; int r = i >> 3; int c4 = (i & 7) * 4;
        pa[p] = *(const float4*)&Xb[(size_t)(n0 + r) * CH + c4];
        pw[p] = *(const float4*)&W[(size_t)(j0 + r) * CH + c4];
    }

    for (int k0 = 0; k0 < CH; k0 += 32) {
        __syncthreads();
        #pragma unroll
        for (int p = 0; p < 4; p++) {
            int i = p * 256 + t; int r = i >> 3; int c4 = (i & 7) * 4;
            As[r * 36 + c4 + 0] = f2tf(pa[p].x);
            As[r * 36 + c4 + 1] = f2tf(pa[p].y);
            As[r * 36 + c4 + 2] = f2tf(pa[p].z);
            As[r * 36 + c4 + 3] = f2tf(pa[p].w);
            Ws[r * 36 + c4 + 0] = f2tf(pw[p].x);
            Ws[r * 36 + c4 + 1] = f2tf(pw[p].y);
            Ws[r * 36 + c4 + 2] = f2tf(pw[p].z);
            Ws[r * 36 + c4 + 3] = f2tf(pw[p].w);
        }
        __syncthreads();
        if (k0 + 32 < CH) {
            #pragma unroll
            for (int p = 0; p < 4; p++) {
                int i = p * 256 + t; int r = i >> 3; int c4 = (i & 7) * 4;
                pa[p] = *(const float4*)&Xb[(size_t)(n0 + r) * CH + k0 + 32 + c4];
                pw[p] = *(const float4*)&W[(size_t)(j0 + r) * CH + k0 + 32 + c4];
            }
        }
        #pragma unroll
        for (int ks = 0; ks < 4; ks++) {
            const int kb = ks * 8;
            uint32_t af[4][4], bf[4][2];
            #pragma unroll
            for (int mt = 0; mt < 4; mt++) {
                int m = wm * 64 + mt * 16;
                af[mt][0] = As[(m + g) * 36 + kb + tig];
                af[mt][1] = As[(m + g + 8) * 36 + kb + tig];
                af[mt][2] = As[(m + g) * 36 + kb + tig + 4];
                af[mt][3] = As[(m + g + 8) * 36 + kb + tig + 4];
            }
            #pragma unroll
            for (int nt = 0; nt < 4; nt++) {
                int n = wn * 32 + nt * 8;
                bf[nt][0] = Ws[(n + g) * 36 + kb + tig];
                bf[nt][1] = Ws[(n + g) * 36 + kb + tig + 4];
            }
            #pragma unroll
            for (int mt = 0; mt < 4; mt++)
                #pragma unroll
                for (int nt = 0; nt < 4; nt++)
                    mma8(acc[mt][nt][0], acc[mt][nt][1], acc[mt][nt][2], acc[mt][nt][3],
                         af[mt][0], af[mt][1], af[mt][2], af[mt][3],
                         bf[nt][0], bf[nt][1]);
        }
    }

    #pragma unroll
    for (int mt = 0; mt < 4; mt++) {
        int n = n0 + wm * 64 + mt * 16 + g;
        #pragma unroll
        for (int nt = 0; nt < 4; nt++) {
            int j = j0 + wn * 32 + nt * 8 + 2 * tig;
            float2 bj = *(const float2*)&bias[j];
            float2 v0 = make_float2(acc[mt][nt][0] + bj.x, acc[mt][nt][1] + bj.y);
            float2 v1 = make_float2(acc[mt][nt][2] + bj.x, acc[mt][nt][3] + bj.y);
            size_t base = (((size_t)b * NH + (j >> 6)) * SEQ) * HD + (j & 63);
            *(float2*)&out[base + (size_t)n * HD]       = v0;
            *(float2*)&out[base + (size_t)(n + 8) * HD] = v1;
        }
    }
}

// ---------------- output projection (same GEMM, flat layout) ---------------------------
__global__ __launch_bounds__(256, 2) void proj_out(
    const float* __restrict__ X, const float* __restrict__ W,
    const float* __restrict__ bias, float* __restrict__ out)
{
    __shared__ uint32_t As[128 * 36];
    __shared__ uint32_t Ws[128 * 36];
    const int b  = blockIdx.z;
    const int n0 = blockIdx.x * 128;
    const int j0 = blockIdx.y * 128;
    const int t  = threadIdx.x;
    const int w  = t >> 5, lane = t & 31;
    const int wm = w & 1, wn = w >> 1;
    const int g  = lane >> 2, tig = lane & 3;
    const float* Xb = X + (size_t)b * SEQ * CH;

    float acc[4][4][4];
    #pragma unroll
    for (int mt = 0; mt < 4; mt++)
        #pragma unroll
        for (int nt = 0; nt < 4; nt++)
            #pragma unroll
            for (int q = 0; q < 4; q++) acc[mt][nt][q] = 0.f;

    float4 pa[4], pw[4];
    #pragma unroll
    for (int p = 0; p < 4; p++) {
        int i = p * 256 + t; int r = i >> 3; int c4 = (i & 7) * 4;
        pa[p] = *(const float4*)&Xb[(size_t)(n0 + r) * CH + c4];
        pw[p] = *(const float4*)&W[(size_t)(j0 + r) * CH + c4];
    }

    for (int k0 = 0; k0 < CH; k0 += 32) {
        __syncthreads();
        #pragma unroll
        for (int p = 0; p < 4; p++) {
            int i = p * 256 + t; int r = i >> 3; int c4 = (i & 7) * 4;
            As[r * 36 + c4 + 0] = f2tf(pa[p].x);
            As[r * 36 + c4 + 1] = f2tf(pa[p].y);
            As[r * 36 + c4 + 2] = f2tf(pa[p].z);
            As[r * 36 + c4 + 3] = f2tf(pa[p].w);
            Ws[r * 36 + c4 + 0] = f2tf(pw[p].x);
            Ws[r * 36 + c4 + 1] = f2tf(pw[p].y);
            Ws[r * 36 + c4 + 2] = f2tf(pw[p].z);
            Ws[r * 36 + c4 + 3] = f2tf(pw[p].w);
        }
        __syncthreads();
        if (k0 + 32 < CH) {
            #pragma unroll
            for (int p = 0; p < 4; p++) {
                int i = p * 256 + t; int r = i >> 3; int c4 = (i & 7) * 4;
                pa[p] = *(const float4*)&Xb[(size_t)(n0 + r) * CH + k0 + 32 + c4];
                pw[p] = *(const float4*)&W[(size_t)(j0 + r) * CH + k0 + 32 + c4];
            }
        }
        #pragma unroll
        for (int ks = 0; ks < 4; ks++) {
            const int kb = ks * 8;
            uint32_t af[4][4], bf[4][2];
            #pragma unroll
            for (int mt = 0; mt < 4; mt++) {
                int m = wm * 64 + mt * 16;
                af[mt][0] = As[(m + g) * 36 + kb + tig];
                af[mt][1] = As[(m + g + 8) * 36 + kb + tig];
                af[mt][2] = As[(m + g) * 36 + kb + tig + 4];
                af[mt][3] = As[(m + g + 8) * 36 + kb + tig + 4];
            }
            #pragma unroll
            for (int nt = 0; nt < 4; nt++) {
                int n = wn * 32 + nt * 8;
                bf[nt][0] = Ws[(n + g) * 36 + kb + tig];
                bf[nt][1] = Ws[(n + g) * 36 + kb + tig + 4];
            }
            #pragma unroll
            for (int mt = 0; mt < 4; mt++)
                #pragma unroll
                for (int nt = 0; nt < 4; nt++)
                    mma8(acc[mt][nt][0], acc[mt][nt][1], acc[mt][nt][2], acc[mt][nt][3],
                         af[mt][0], af[mt][1], af[mt][2], af[mt][3],
                         bf[nt][0], bf[nt][1]);
        }
    }

    #pragma unroll
    for (int mt = 0; mt < 4; mt++) {
        int n = n0 + wm * 64 + mt * 16 + g;
        #pragma unroll
        for (int nt = 0; nt < 4; nt++) {
            int j = j0 + wn * 32 + nt * 8 + 2 * tig;
            float2 bj = *(const float2*)&bias[j];
            *(float2*)&out[((size_t)b * SEQ + n) * CH + j] =
                make_float2(acc[mt][nt][0] + bj.x, acc[mt][nt][1] + bj.y);
            *(float2*)&out[((size_t)b * SEQ + n + 8) * CH + j] =
                make_float2(acc[mt][nt][2] + bj.x, acc[mt][nt][3] + bj.y);
        }
    }
}

// ---------------- flash attention: fragment-space gumbel softmax, no max ---------------
// w = exp2(logit*SCALE*log2e) / (-log u): exact softmax fusion, no overflow for this
// problem's ranges, so no online max / correction. Row sums stay in registers.
__global__ __launch_bounds__(256, 2) void attn_mma(
    const float* __restrict__ Q, const float* __restrict__ K,
    const float* __restrict__ V, float* __restrict__ out)
{
    extern __shared__ uint32_t sm[];
    uint32_t* Qs = sm;                       // [64][68] tf32
    uint32_t* Ks = sm + 4352;                // [64][68] tf32
    uint32_t* Vs = sm + 8704;                // [64][72] tf32
    uint32_t* Su = sm + 13312;               // [64][68] P (tf32 bits)
    float*    l_s = (float*)(sm + 17664);    // [64] row sums

    const int b = blockIdx.z, h = blockIdx.y, n0 = blockIdx.x * 64;
    const int t = threadIdx.x, w = t >> 5, lane = t & 31;
    const int wm = w & 3, wn = w >> 2;
    const int g = lane >> 2, tig = lane & 3;

    const float* Qg = Q + (((size_t)b * NH + h) * SEQ + n0) * HD;
    const float* Kg = K + ((size_t)b * NH + h) * SEQ * HD;
    const float* Vg = V + ((size_t)b * NH + h) * SEQ * HD;

    #pragma unroll
    for (int p = 0; p < 4; p++) {
        int i = p * 256 + t; int r = i >> 4; int c4 = (i & 15) * 4;
        float4 v = *(const float4*)&Qg[r * HD + c4];
        Qs[r * 68 + c4 + 0] = f2tf(v.x);
        Qs[r * 68 + c4 + 1] = f2tf(v.y);
        Qs[r * 68 + c4 + 2] = f2tf(v.z);
        Qs[r * 68 + c4 + 3] = f2tf(v.w);
    }
    if (t < 64) l_s[t] = 0.f;

    float acc_o[4][4];
    #pragma unroll
    for (int nt = 0; nt < 4; nt++)
        #pragma unroll
        for (int q = 0; q < 4; q++) acc_o[nt][q] = 0.f;

    const int r0 = wm * 16 + g;
    const int r1 = r0 + 8;
    const uint32_t bh = (uint32_t)(b * NH + h);
    const uint32_t base0 = ((bh << 11) + (uint32_t)(n0 + r0)) << 11;
    const uint32_t base1 = base0 + (8u << 11);
    float lr0 = 0.f, lr1 = 0.f;

    for (int k0 = 0; k0 < SEQ; k0 += 64) {
        __syncthreads();
        #pragma unroll
        for (int p = 0; p < 4; p++) {
            int i = p * 256 + t; int r = i >> 4; int c4 = (i & 15) * 4;
            float4 kv = *(const float4*)&Kg[(size_t)(k0 + r) * HD + c4];
            Ks[r * 68 + c4 + 0] = f2tf(kv.x);
            Ks[r * 68 + c4 + 1] = f2tf(kv.y);
            Ks[r * 68 + c4 + 2] = f2tf(kv.z);
            Ks[r * 68 + c4 + 3] = f2tf(kv.w);
            float4 vv = *(const float4*)&Vg[(size_t)(k0 + r) * HD + c4];
            Vs[r * 72 + c4 + 0] = f2tf(vv.x);
            Vs[r * 72 + c4 + 1] = f2tf(vv.y);
            Vs[r * 72 + c4 + 2] = f2tf(vv.z);
            Vs[r * 72 + c4 + 3] = f2tf(vv.w);
        }
        __syncthreads();

        // --- S = Q K^T on fragments ---
        float acc_s[4][4];
        #pragma unroll
        for (int nt = 0; nt < 4; nt++)
            #pragma unroll
            for (int q = 0; q < 4; q++) acc_s[nt][q] = 0.f;
        #pragma unroll
        for (int ks = 0; ks < 8; ks++) {
            const int kb = ks * 8;
            const int m = wm * 16;
            uint32_t a0 = Qs[(m + g) * 68 + kb + tig];
            uint32_t a1 = Qs[(m + g + 8) * 68 + kb + tig];
            uint32_t a2 = Qs[(m + g) * 68 + kb + tig + 4];
            uint32_t a3 = Qs[(m + g + 8) * 68 + kb + tig + 4];
            #pragma unroll
            for (int nt = 0; nt < 4; nt++) {
                int n = wn * 32 + nt * 8;
                uint32_t b0 = Ks[(n + g) * 68 + kb + tig];
                uint32_t b1 = Ks[(n + g) * 68 + kb + tig + 4];
                mma8(acc_s[nt][0], acc_s[nt][1], acc_s[nt][2], acc_s[nt][3],
                     a0, a1, a2, a3, b0, b1);
            }
        }

        // --- fragment-space gumbel weights: w = exp2(s*SC2) * rcp(-log u) ---
        #pragma unroll
        for (int nt = 0; nt < 4; nt++) {
            const uint32_t c0 = (uint32_t)(wn * 32 + nt * 8 + 2 * tig);
            const uint32_t i00 = base0 + (uint32_t)k0 + c0;
            const uint32_t i10 = base1 + (uint32_t)k0 + c0;
            float t00 = neglog_u_at(i00);
            float t01 = neglog_u_at(i00 + 1u);
            float t10 = neglog_u_at(i10);
            float t11 = neglog_u_at(i10 + 1u);
            float w00 = ex2(acc_s[nt][0] * SC2) * frcp(t00);
            float w01 = ex2(acc_s[nt][1] * SC2) * frcp(t01);
            float w10 = ex2(acc_s[nt][2] * SC2) * frcp(t10);
            float w11 = ex2(acc_s[nt][3] * SC2) * frcp(t11);
            lr0 += w00 + w01;
            lr1 += w10 + w11;
            uint2 p0 = make_uint2(f2tf(w00), f2tf(w01));
            uint2 p1 = make_uint2(f2tf(w10), f2tf(w11));
            *(uint2*)&Su[r0 * 68 + c0] = p0;
            *(uint2*)&Su[r1 * 68 + c0] = p1;
        }
        __syncthreads();

        // --- O += P V ---
        #pragma unroll
        for (int ks = 0; ks < 8; ks++) {
            const int kb = ks * 8;
            const int m = wm * 16;
            uint32_t a0 = Su[(m + g) * 68 + kb + tig];
            uint32_t a1 = Su[(m + g + 8) * 68 + kb + tig];
            uint32_t a2 = Su[(m + g) * 68 + kb + tig + 4];
            uint32_t a3 = Su[(m + g + 8) * 68 + kb + tig + 4];
            #pragma unroll
            for (int nt = 0; nt < 4; nt++) {
                int n = wn * 32 + nt * 8;
                uint32_t b0 = Vs[(kb + tig) * 72 + n + g];
                uint32_t b1 = Vs[(kb + tig + 4) * 72 + n + g];
                mma8(acc_o[nt][0], acc_o[nt][1], acc_o[nt][2], acc_o[nt][3],
                     a0, a1, a2, a3, b0, b1);
            }
        }
    }

    // --- reduce row sums: 4 tig-lanes per row, then 2 warps (wn) via smem atomics ---
    lr0 += __shfl_xor_sync(0xffffffffu, lr0, 1);
    lr0 += __shfl_xor_sync(0xffffffffu, lr0, 2);
    lr1 += __shfl_xor_sync(0xffffffffu, lr1, 1);
    lr1 += __shfl_xor_sync(0xffffffffu, lr1, 2);
    if (tig == 0) {
        atomicAdd(&l_s[r0], lr0);
        atomicAdd(&l_s[r1], lr1);
    }
    __syncthreads();

    // --- epilogue: normalize, write [B, N, C] with c = h*64 + d ---
    float inv0 = 1.0f / l_s[r0];
    float inv1 = 1.0f / l_s[r1];
    #pragma unroll
    for (int nt = 0; nt < 4; nt++) {
        int d = wn * 32 + nt * 8 + 2 * tig;
        *(float2*)&out[((size_t)b * SEQ + n0 + r0) * CH + h * HD + d] =
            make_float2(acc_o[nt][0] * inv0, acc_o[nt][1] * inv0);
        *(float2*)&out[((size_t)b * SEQ + n0 + r1) * CH + h * HD + d] =
            make_float2(acc_o[nt][2] * inv1, acc_o[nt][3] * inv1);
    }
}

// ---------------- launch ----------------------------------------------------------------
extern "C" void kernel_launch(void* const* d_in, const int* in_sizes, int n_in,
                              void* d_out, int out_size)
{
    (void)in_sizes; (void)n_in; (void)out_size;
    const float* x  = (const float*)d_in[0];
    const float* y  = (const float*)d_in[1];
    const float* z  = (const float*)d_in[2];
    const float* Wq = (const float*)d_in[3];
    const float* bq = (const float*)d_in[4];
    const float* Wk = (const float*)d_in[5];
    const float* bk = (const float*)d_in[6];
    const float* Wv = (const float*)d_in[7];
    const float* bv = (const float*)d_in[8];
    const float* Wo = (const float*)d_in[9];
    const float* bo = (const float*)d_in[10];
    float* out = (float*)d_out;

    float *qp, *kp, *vp, *ap;
    cudaGetSymbolAddress((void**)&qp, g_Q);
    cudaGetSymbolAddress((void**)&kp, g_K);
    cudaGetSymbolAddress((void**)&vp, g_V);
    cudaGetSymbolAddress((void**)&ap, g_attn);

    dim3 pb(256);
    dim3 qkvg(SEQ / 128, CH / 128, NB * 3);
    proj_qkv<<<qkvg, pb>>>(x, y, z, Wq, bq, Wk, bk, Wv, bv, qp, kp, vp);

    const int SMEM = (17664 + 64) * 4;  // 70912 B
    cudaFuncSetAttribute(attn_mma, cudaFuncAttributeMaxDynamicSharedMemorySize, SMEM);
    dim3 ag(SEQ / 64, NH, NB);
    attn_mma<<<ag, pb, SMEM>>>(qp, kp, vp, ap);

    dim3 pg(SEQ / 128, CH / 128, NB);
    proj_out<<<pg, pb>>>(ap, Wo, bo, out);
}

// round 4
// speedup vs baseline: 2.9179x; 1.0999x over previous
#include <cuda_runtime.h>
#include <stdint.h>

#define NB 4
#define SEQ 2048
#define CH 512
#define NH 8
#define HD 64
#define SCALE 0.125f
// SCALE * log2(e)
#define SC2 0.18033688011112042f

// ---------------- device scratch (allocation-free rule: static globals) ----------------
__device__ float g_Q[(size_t)NB * NH * SEQ * HD];
__device__ float g_K[(size_t)NB * NH * SEQ * HD];
__device__ float g_V[(size_t)NB * NH * SEQ * HD];
__device__ float g_attn[(size_t)NB * SEQ * CH];

// ---------------- helpers ---------------------------------------------------------------
__device__ __forceinline__ uint32_t f2tf(float f) {
    uint32_t r;
    asm("cvt.rna.tf32.f32 %0, %1;" : "=r"(r) : "f"(f));
    return r;
}

__device__ __forceinline__ float ex2(float x) {
    float r;
    asm("ex2.approx.ftz.f32 %0, %1;" : "=f"(r) : "f"(x));
    return r;
}

__device__ __forceinline__ float frcp(float x) {
    float r;
    asm("rcp.approx.ftz.f32 %0, %1;" : "=f"(r) : "f"(x));
    return r;
}

__device__ __forceinline__ void mma8(float& d0, float& d1, float& d2, float& d3,
                                     uint32_t a0, uint32_t a1, uint32_t a2, uint32_t a3,
                                     uint32_t b0, uint32_t b1) {
    asm volatile(
        "mma.sync.aligned.m16n8k8.row.col.f32.tf32.tf32.f32 "
        "{%0,%1,%2,%3},{%4,%5,%6,%7},{%8,%9},{%0,%1,%2,%3};"
        : "+f"(d0), "+f"(d1), "+f"(d2), "+f"(d3)
        : "r"(a0), "r"(a1), "r"(a2), "r"(a3), "r"(b0), "r"(b1));
}

// ---------------- JAX threefry2x32, partitionable: bits for flat index ------------------
__device__ __forceinline__ uint32_t tf_bits(uint32_t idx) {
    const uint32_t ks0 = 0u, ks1 = 42u, ks2 = 0x1BD11BF0u;
    uint32_t x0 = ks0;
    uint32_t x1 = idx + ks1;
#define TF_R(r) { x0 += x1; x1 = __funnelshift_l(x1, x1, (r)); x1 ^= x0; }
    TF_R(13) TF_R(15) TF_R(26) TF_R(6)   x0 += ks1; x1 += ks2 + 1u;
    TF_R(17) TF_R(29) TF_R(16) TF_R(24)  x0 += ks2; x1 += ks0 + 2u;
    TF_R(13) TF_R(15) TF_R(26) TF_R(6)   x0 += ks0; x1 += ks1 + 3u;
    TF_R(17) TF_R(29) TF_R(16) TF_R(24)  x0 += ks1; x1 += ks2 + 4u;
    TF_R(13) TF_R(15) TF_R(26) TF_R(6)   x0 += ks2; x1 += ks0 + 5u;
#undef TF_R
    return x0 ^ x1;
}

// ---------------- hybrid -log(u): MUFU lg2 fast path + exact series near u->1 ----------
// u = ((bits>>9)|0x3f800000) - 1 in [0,1). For d = 1-u <= 2^-7 the MUFU absolute error
// would be large relative error, so use -log(1-d) = d + d^2/2 + d^3/3 (d exact).
__device__ __forceinline__ float neglog_u(uint32_t bits) {
    float v = __uint_as_float((bits >> 9) | 0x3f800000u);  // [1,2)
    float u = v - 1.0f;                                    // exact
    float l;
    asm("lg2.approx.ftz.f32 %0, %1;" : "=f"(l) : "f"(u));
    float t1 = -0.6931471805599453f * l;
    float d = 2.0f - v;                                    // = 1-u, exact
    float t2 = d * fmaf(d, fmaf(d, 0.3333333333f, 0.5f), 1.0f);
    return (d < 0.0078125f) ? t2 : t1;
}

// ---------------- fused QKV projection GEMM via tf32 mma -------------------------------
__global__ __launch_bounds__(256, 2) void proj_qkv(
    const float* __restrict__ x, const float* __restrict__ y, const float* __restrict__ z,
    const float* __restrict__ Wq, const float* __restrict__ bq,
    const float* __restrict__ Wk, const float* __restrict__ bk,
    const float* __restrict__ Wv, const float* __restrict__ bv,
    float* __restrict__ oq, float* __restrict__ ok, float* __restrict__ ov)
{
    __shared__ uint32_t As[128 * 36];
    __shared__ uint32_t Ws[128 * 36];
    const int b     = blockIdx.z & 3;
    const int which = blockIdx.z >> 2;
    const float* X    = (which == 0) ? x  : (which == 1) ? y  : z;
    const float* W    = (which == 0) ? Wq : (which == 1) ? Wk : Wv;
    const float* bias = (which == 0) ? bq : (which == 1) ? bk : bv;
    float* out        = (which == 0) ? oq : (which == 1) ? ok : ov;

    const int n0 = blockIdx.x * 128;
    const int j0 = blockIdx.y * 128;
    const int t  = threadIdx.x;
    const int w  = t >> 5, lane = t & 31;
    const int wm = w & 1, wn = w >> 1;
    const int g  = lane >> 2, tig = lane & 3;
    const float* Xb = X + (size_t)b * SEQ * CH;

    float acc[4][4][4];
    #pragma unroll
    for (int mt = 0; mt < 4; mt++)
        #pragma unroll
        for (int nt = 0; nt < 4; nt++)
            #pragma unroll
            for (int q = 0; q < 4; q++) acc[mt][nt][q] = 0.f;

    float4 pa[4], pw[4];
    #pragma unroll
    for (int p = 0; p < 4; p++) {
        int i = p * 256 + t; int r = i >> 3; int c4 = (i & 7) * 4;
        pa[p] = *(const float4*)&Xb[(size_t)(n0 + r) * CH + c4];
        pw[p] = *(const float4*)&W[(size_t)(j0 + r) * CH + c4];
    }

    for (int k0 = 0; k0 < CH; k0 += 32) {
        __syncthreads();
        #pragma unroll
        for (int p = 0; p < 4; p++) {
            int i = p * 256 + t; int r = i >> 3; int c4 = (i & 7) * 4;
            As[r * 36 + c4 + 0] = f2tf(pa[p].x);
            As[r * 36 + c4 + 1] = f2tf(pa[p].y);
            As[r * 36 + c4 + 2] = f2tf(pa[p].z);
            As[r * 36 + c4 + 3] = f2tf(pa[p].w);
            Ws[r * 36 + c4 + 0] = f2tf(pw[p].x);
            Ws[r * 36 + c4 + 1] = f2tf(pw[p].y);
            Ws[r * 36 + c4 + 2] = f2tf(pw[p].z);
            Ws[r * 36 + c4 + 3] = f2tf(pw[p].w);
        }
        __syncthreads();
        if (k0 + 32 < CH) {
            #pragma unroll
            for (int p = 0; p < 4; p++) {
                int i = p * 256 + t; int r = i >> 3; int c4 = (i & 7) * 4;
                pa[p] = *(const float4*)&Xb[(size_t)(n0 + r) * CH + k0 + 32 + c4];
                pw[p] = *(const float4*)&W[(size_t)(j0 + r) * CH + k0 + 32 + c4];
            }
        }
        #pragma unroll
        for (int ks = 0; ks < 4; ks++) {
            const int kb = ks * 8;
            uint32_t af[4][4], bf[4][2];
            #pragma unroll
            for (int mt = 0; mt < 4; mt++) {
                int m = wm * 64 + mt * 16;
                af[mt][0] = As[(m + g) * 36 + kb + tig];
                af[mt][1] = As[(m + g + 8) * 36 + kb + tig];
                af[mt][2] = As[(m + g) * 36 + kb + tig + 4];
                af[mt][3] = As[(m + g + 8) * 36 + kb + tig + 4];
            }
            #pragma unroll
            for (int nt = 0; nt < 4; nt++) {
                int n = wn * 32 + nt * 8;
                bf[nt][0] = Ws[(n + g) * 36 + kb + tig];
                bf[nt][1] = Ws[(n + g) * 36 + kb + tig + 4];
            }
            #pragma unroll
            for (int mt = 0; mt < 4; mt++)
                #pragma unroll
                for (int nt = 0; nt < 4; nt++)
                    mma8(acc[mt][nt][0], acc[mt][nt][1], acc[mt][nt][2], acc[mt][nt][3],
                         af[mt][0], af[mt][1], af[mt][2], af[mt][3],
                         bf[nt][0], bf[nt][1]);
        }
    }

    #pragma unroll
    for (int mt = 0; mt < 4; mt++) {
        int n = n0 + wm * 64 + mt * 16 + g;
        #pragma unroll
        for (int nt = 0; nt < 4; nt++) {
            int j = j0 + wn * 32 + nt * 8 + 2 * tig;
            float2 bj = *(const float2*)&bias[j];
            float2 v0 = make_float2(acc[mt][nt][0] + bj.x, acc[mt][nt][1] + bj.y);
            float2 v1 = make_float2(acc[mt][nt][2] + bj.x, acc[mt][nt][3] + bj.y);
            size_t base = (((size_t)b * NH + (j >> 6)) * SEQ) * HD + (j & 63);
            *(float2*)&out[base + (size_t)n * HD]       = v0;
            *(float2*)&out[base + (size_t)(n + 8) * HD] = v1;
        }
    }
}

// ---------------- output projection (same GEMM, flat layout) ---------------------------
__global__ __launch_bounds__(256, 2) void proj_out(
    const float* __restrict__ X, const float* __restrict__ W,
    const float* __restrict__ bias, float* __restrict__ out)
{
    __shared__ uint32_t As[128 * 36];
    __shared__ uint32_t Ws[128 * 36];
    const int b  = blockIdx.z;
    const int n0 = blockIdx.x * 128;
    const int j0 = blockIdx.y * 128;
    const int t  = threadIdx.x;
    const int w  = t >> 5, lane = t & 31;
    const int wm = w & 1, wn = w >> 1;
    const int g  = lane >> 2, tig = lane & 3;
    const float* Xb = X + (size_t)b * SEQ * CH;

    float acc[4][4][4];
    #pragma unroll
    for (int mt = 0; mt < 4; mt++)
        #pragma unroll
        for (int nt = 0; nt < 4; nt++)
            #pragma unroll
            for (int q = 0; q < 4; q++) acc[mt][nt][q] = 0.f;

    float4 pa[4], pw[4];
    #pragma unroll
    for (int p = 0; p < 4; p++) {
        int i = p * 256 + t; int r = i >> 3; int c4 = (i & 7) * 4;
        pa[p] = *(const float4*)&Xb[(size_t)(n0 + r) * CH + c4];
        pw[p] = *(const float4*)&W[(size_t)(j0 + r) * CH + c4];
    }

    for (int k0 = 0; k0 < CH; k0 += 32) {
        __syncthreads();
        #pragma unroll
        for (int p = 0; p < 4; p++) {
            int i = p * 256 + t; int r = i >> 3; int c4 = (i & 7) * 4;
            As[r * 36 + c4 + 0] = f2tf(pa[p].x);
            As[r * 36 + c4 + 1] = f2tf(pa[p].y);
            As[r * 36 + c4 + 2] = f2tf(pa[p].z);
            As[r * 36 + c4 + 3] = f2tf(pa[p].w);
            Ws[r * 36 + c4 + 0] = f2tf(pw[p].x);
            Ws[r * 36 + c4 + 1] = f2tf(pw[p].y);
            Ws[r * 36 + c4 + 2] = f2tf(pw[p].z);
            Ws[r * 36 + c4 + 3] = f2tf(pw[p].w);
        }
        __syncthreads();
        if (k0 + 32 < CH) {
            #pragma unroll
            for (int p = 0; p < 4; p++) {
                int i = p * 256 + t; int r = i >> 3; int c4 = (i & 7) * 4;
                pa[p] = *(const float4*)&Xb[(size_t)(n0 + r) * CH + k0 + 32 + c4];
                pw[p] = *(const float4*)&W[(size_t)(j0 + r) * CH + k0 + 32 + c4];
            }
        }
        #pragma unroll
        for (int ks = 0; ks < 4; ks++) {
            const int kb = ks * 8;
            uint32_t af[4][4], bf[4][2];
            #pragma unroll
            for (int mt = 0; mt < 4; mt++) {
                int m = wm * 64 + mt * 16;
                af[mt][0] = As[(m + g) * 36 + kb + tig];
                af[mt][1] = As[(m + g + 8) * 36 + kb + tig];
                af[mt][2] = As[(m + g) * 36 + kb + tig + 4];
                af[mt][3] = As[(m + g + 8) * 36 + kb + tig + 4];
            }
            #pragma unroll
            for (int nt = 0; nt < 4; nt++) {
                int n = wn * 32 + nt * 8;
                bf[nt][0] = Ws[(n + g) * 36 + kb + tig];
                bf[nt][1] = Ws[(n + g) * 36 + kb + tig + 4];
            }
            #pragma unroll
            for (int mt = 0; mt < 4; mt++)
                #pragma unroll
                for (int nt = 0; nt < 4; nt++)
                    mma8(acc[mt][nt][0], acc[mt][nt][1], acc[mt][nt][2], acc[mt][nt][3],
                         af[mt][0], af[mt][1], af[mt][2], af[mt][3],
                         bf[nt][0], bf[nt][1]);
        }
    }

    #pragma unroll
    for (int mt = 0; mt < 4; mt++) {
        int n = n0 + wm * 64 + mt * 16 + g;
        #pragma unroll
        for (int nt = 0; nt < 4; nt++) {
            int j = j0 + wn * 32 + nt * 8 + 2 * tig;
            float2 bj = *(const float2*)&bias[j];
            *(float2*)&out[((size_t)b * SEQ + n) * CH + j] =
                make_float2(acc[mt][nt][0] + bj.x, acc[mt][nt][1] + bj.y);
            *(float2*)&out[((size_t)b * SEQ + n + 8) * CH + j] =
                make_float2(acc[mt][nt][2] + bj.x, acc[mt][nt][3] + bj.y);
        }
    }
}

// ---------------- flash attention: fragment-space gumbel softmax -----------------------
// Warp layout: wm = w>>1 (4 row-groups), wn = w&1 (2 col-halves); the two warps of a
// wm-pair are contiguous (threads 64*wm .. 64*wm+63) so the Su write->PV read hand-off
// uses a 64-thread named barrier instead of a full block barrier.
// 3 CTAs/SM (<=80 regs forced); smem 70912 B * 3 = 212.7 KB fits.
__global__ __launch_bounds__(256, 3) void attn_mma(
    const float* __restrict__ Q, const float* __restrict__ K,
    const float* __restrict__ V, float* __restrict__ out)
{
    extern __shared__ uint32_t sm[];
    uint32_t* Qs = sm;                       // [64][68] tf32
    uint32_t* Ks = sm + 4352;                // [64][68] tf32
    uint32_t* Vs = sm + 8704;                // [64][72] tf32
    uint32_t* Su = sm + 13312;               // [64][68] P (tf32 bits)
    float*    l_s = (float*)(sm + 17664);    // [64] row sums

    const int b = blockIdx.z, h = blockIdx.y, n0 = blockIdx.x * 64;
    const int t = threadIdx.x, w = t >> 5, lane = t & 31;
    const int wm = w >> 1, wn = w & 1;
    const int g = lane >> 2, tig = lane & 3;

    const float* Qg = Q + (((size_t)b * NH + h) * SEQ + n0) * HD;
    const float* Kg = K + ((size_t)b * NH + h) * SEQ * HD;
    const float* Vg = V + ((size_t)b * NH + h) * SEQ * HD;

    #pragma unroll
    for (int p = 0; p < 4; p++) {
        int i = p * 256 + t; int r = i >> 4; int c4 = (i & 15) * 4;
        float4 v = *(const float4*)&Qg[r * HD + c4];
        Qs[r * 68 + c4 + 0] = f2tf(v.x);
        Qs[r * 68 + c4 + 1] = f2tf(v.y);
        Qs[r * 68 + c4 + 2] = f2tf(v.z);
        Qs[r * 68 + c4 + 3] = f2tf(v.w);
    }
    if (t < 64) l_s[t] = 0.f;

    float acc_o[4][4];
    #pragma unroll
    for (int nt = 0; nt < 4; nt++)
        #pragma unroll
        for (int q = 0; q < 4; q++) acc_o[nt][q] = 0.f;

    const int r0 = wm * 16 + g;
    const int r1 = r0 + 8;
    const uint32_t bh = (uint32_t)(b * NH + h);
    const uint32_t base0 = ((bh << 11) + (uint32_t)(n0 + r0)) << 11;
    const uint32_t base1 = base0 + (8u << 11);
    float lr0 = 0.f, lr1 = 0.f;

    for (int k0 = 0; k0 < SEQ; k0 += 64) {
        __syncthreads();   // prev tile's mma readers done with Ks/Vs/Su
        #pragma unroll
        for (int p = 0; p < 4; p++) {
            int i = p * 256 + t; int r = i >> 4; int c4 = (i & 15) * 4;
            float4 kv = *(const float4*)&Kg[(size_t)(k0 + r) * HD + c4];
            Ks[r * 68 + c4 + 0] = f2tf(kv.x);
            Ks[r * 68 + c4 + 1] = f2tf(kv.y);
            Ks[r * 68 + c4 + 2] = f2tf(kv.z);
            Ks[r * 68 + c4 + 3] = f2tf(kv.w);
            float4 vv = *(const float4*)&Vg[(size_t)(k0 + r) * HD + c4];
            Vs[r * 72 + c4 + 0] = f2tf(vv.x);
            Vs[r * 72 + c4 + 1] = f2tf(vv.y);
            Vs[r * 72 + c4 + 2] = f2tf(vv.z);
            Vs[r * 72 + c4 + 3] = f2tf(vv.w);
        }
        __syncthreads();

        // --- S = Q K^T on fragments ---
        float acc_s[4][4];
        #pragma unroll
        for (int nt = 0; nt < 4; nt++)
            #pragma unroll
            for (int q = 0; q < 4; q++) acc_s[nt][q] = 0.f;
        #pragma unroll
        for (int ks = 0; ks < 8; ks++) {
            const int kb = ks * 8;
            const int m = wm * 16;
            uint32_t a0 = Qs[(m + g) * 68 + kb + tig];
            uint32_t a1 = Qs[(m + g + 8) * 68 + kb + tig];
            uint32_t a2 = Qs[(m + g) * 68 + kb + tig + 4];
            uint32_t a3 = Qs[(m + g + 8) * 68 + kb + tig + 4];
            #pragma unroll
            for (int nt = 0; nt < 4; nt++) {
                int n = wn * 32 + nt * 8;
                uint32_t b0 = Ks[(n + g) * 68 + kb + tig];
                uint32_t b1 = Ks[(n + g) * 68 + kb + tig + 4];
                mma8(acc_s[nt][0], acc_s[nt][1], acc_s[nt][2], acc_s[nt][3],
                     a0, a1, a2, a3, b0, b1);
            }
        }

        // --- fragment-space gumbel weights: w = exp2(s*SC2) * rcp(-log u) ---
        #pragma unroll
        for (int nt = 0; nt < 4; nt++) {
            const uint32_t c0 = (uint32_t)(wn * 32 + nt * 8 + 2 * tig);
            const uint32_t i00 = base0 + (uint32_t)k0 + c0;
            const uint32_t i10 = base1 + (uint32_t)k0 + c0;
            float t00 = neglog_u(tf_bits(i00));
            float t01 = neglog_u(tf_bits(i00 + 1u));
            float t10 = neglog_u(tf_bits(i10));
            float t11 = neglog_u(tf_bits(i10 + 1u));
            float w00 = ex2(acc_s[nt][0] * SC2) * frcp(t00);
            float w01 = ex2(acc_s[nt][1] * SC2) * frcp(t01);
            float w10 = ex2(acc_s[nt][2] * SC2) * frcp(t10);
            float w11 = ex2(acc_s[nt][3] * SC2) * frcp(t11);
            lr0 += w00 + w01;
            lr1 += w10 + w11;
            uint2 p0 = make_uint2(f2tf(w00), f2tf(w01));
            uint2 p1 = make_uint2(f2tf(w10), f2tf(w11));
            *(uint2*)&Su[r0 * 68 + c0] = p0;
            *(uint2*)&Su[r1 * 68 + c0] = p1;
        }
        // pair barrier: both wn halves of this wm row-group finished writing Su rows
        asm volatile("bar.sync %0, 64;" :: "r"(1 + wm) : "memory");

        // --- O += P V (A rows are this pair's own Su rows) ---
        #pragma unroll
        for (int ks = 0; ks < 8; ks++) {
            const int kb = ks * 8;
            const int m = wm * 16;
            uint32_t a0 = Su[(m + g) * 68 + kb + tig];
            uint32_t a1 = Su[(m + g + 8) * 68 + kb + tig];
            uint32_t a2 = Su[(m + g) * 68 + kb + tig + 4];
            uint32_t a3 = Su[(m + g + 8) * 68 + kb + tig + 4];
            #pragma unroll
            for (int nt = 0; nt < 4; nt++) {
                int n = wn * 32 + nt * 8;
                uint32_t b0 = Vs[(kb + tig) * 72 + n + g];
                uint32_t b1 = Vs[(kb + tig + 4) * 72 + n + g];
                mma8(acc_o[nt][0], acc_o[nt][1], acc_o[nt][2], acc_o[nt][3],
                     a0, a1, a2, a3, b0, b1);
            }
        }
    }

    // --- reduce row sums: 4 tig-lanes per row, then across wn via smem atomics ---
    lr0 += __shfl_xor_sync(0xffffffffu, lr0, 1);
    lr0 += __shfl_xor_sync(0xffffffffu, lr0, 2);
    lr1 += __shfl_xor_sync(0xffffffffu, lr1, 1);
    lr1 += __shfl_xor_sync(0xffffffffu, lr1, 2);
    if (tig == 0) {
        atomicAdd(&l_s[r0], lr0);
        atomicAdd(&l_s[r1], lr1);
    }
    __syncthreads();

    // --- epilogue: normalize, write [B, N, C] with c = h*64 + d ---
    float inv0 = 1.0f / l_s[r0];
    float inv1 = 1.0f / l_s[r1];
    #pragma unroll
    for (int nt = 0; nt < 4; nt++) {
        int d = wn * 32 + nt * 8 + 2 * tig;
        *(float2*)&out[((size_t)b * SEQ + n0 + r0) * CH + h * HD + d] =
            make_float2(acc_o[nt][0] * inv0, acc_o[nt][1] * inv0);
        *(float2*)&out[((size_t)b * SEQ + n0 + r1) * CH + h * HD + d] =
            make_float2(acc_o[nt][2] * inv1, acc_o[nt][3] * inv1);
    }
}

// ---------------- launch ----------------------------------------------------------------
extern "C" void kernel_launch(void* const* d_in, const int* in_sizes, int n_in,
                              void* d_out, int out_size)
{
    (void)in_sizes; (void)n_in; (void)out_size;
    const float* x  = (const float*)d_in[0];
    const float* y  = (const float*)d_in[1];
    const float* z  = (const float*)d_in[2];
    const float* Wq = (const float*)d_in[3];
    const float* bq = (const float*)d_in[4];
    const float* Wk = (const float*)d_in[5];
    const float* bk = (const float*)d_in[6];
    const float* Wv = (const float*)d_in[7];
    const float* bv = (const float*)d_in[8];
    const float* Wo = (const float*)d_in[9];
    const float* bo = (const float*)d_in[10];
    float* out = (float*)d_out;

    float *qp, *kp, *vp, *ap;
    cudaGetSymbolAddress((void**)&qp, g_Q);
    cudaGetSymbolAddress((void**)&kp, g_K);
    cudaGetSymbolAddress((void**)&vp, g_V);
    cudaGetSymbolAddress((void**)&ap, g_attn);

    dim3 pb(256);
    dim3 qkvg(SEQ / 128, CH / 128, NB * 3);
    proj_qkv<<<qkvg, pb>>>(x, y, z, Wq, bq, Wk, bk, Wv, bv, qp, kp, vp);

    const int SMEM = (17664 + 64) * 4;  // 70912 B
    cudaFuncSetAttribute(attn_mma, cudaFuncAttributeMaxDynamicSharedMemorySize, SMEM);
    dim3 ag(SEQ / 64, NH, NB);
    attn_mma<<<ag, pb, SMEM>>>(qp, kp, vp, ap);

    dim3 pg(SEQ / 128, CH / 128, NB);
    proj_out<<<pg, pb>>>(ap, Wo, bo, out);
}